// round 5
// baseline (speedup 1.0000x reference)
#include <cuda_runtime.h>

#define BB 32
#define NN 128
#define HH 100
#define HP 128          // padded h
#define ROWS (BB*NN)    // 4096

// Scratch (static device allocations — allowed)
__device__ float g_hidden[ROWS*HH];
__device__ float g_hv[ROWS*HH];
__device__ float g_hw[ROWS*HH];
__device__ float g_msg[ROWS*HH];
__device__ float g_gterm[ROWS*HH];
__device__ int   g_nodemask[ROWS];
// padded weights: [k][128], zeros for h >= 100
__device__ float g_Wv_p[100*HP];
__device__ float g_Ww_p[100*HP];
__device__ float g_Wu_p[200*HP];
__device__ float g_Wr_p[200*HP];

typedef unsigned long long u64;

__device__ __forceinline__ u64 fma2(u64 a, u64 b, u64 c) {
    u64 d;
    asm("fma.rn.f32x2 %0, %1, %2, %3;" : "=l"(d) : "l"(a), "l"(b), "l"(c));
    return d;
}
__device__ __forceinline__ u64 pack2(float w) {
    u64 d;
    asm("mov.b64 %0, {%1, %1};" : "=l"(d) : "f"(w));
    return d;
}
__device__ __forceinline__ void unpack2(u64 v, float& lo, float& hi) {
    asm("mov.b64 {%0, %1}, %2;" : "=f"(lo), "=f"(hi) : "l"(v));
}

// ---------------------------------------------------------------------------
// prep: pad weights to [k][128] with zero columns for h in [100,128)
// ---------------------------------------------------------------------------
__global__ void k_prep(const float* __restrict__ Wv, const float* __restrict__ Ww,
                       const float* __restrict__ Wu, const float* __restrict__ Wr) {
    int i = blockIdx.x * 256 + threadIdx.x;
    if (i < 12800) {
        int k = i >> 7, h = i & 127;
        g_Wv_p[i] = (h < HH) ? Wv[k*HH + h] : 0.f;
    } else if (i < 25600) {
        int j = i - 12800; int k = j >> 7, h = j & 127;
        g_Ww_p[j] = (h < HH) ? Ww[k*HH + h] : 0.f;
    } else if (i < 51200) {
        int j = i - 25600; int k = j >> 7, h = j & 127;
        g_Wu_p[j] = (h < HH) ? Wu[k*HH + h] : 0.f;
    } else if (i < 76800) {
        int j = i - 51200; int k = j >> 7, h = j & 127;
        g_Wr_p[j] = (h < HH) ? Wr[k*HH + h] : 0.f;
    }
}

// ---------------------------------------------------------------------------
// init: hidden = nodes; node_mask[row] = (sum_w sum_e edges[row,w,e]) != 0
// ---------------------------------------------------------------------------
__global__ void k_init(const float* __restrict__ nodes,
                       const float* __restrict__ edges) {
    int row = blockIdx.x;
    int tid = threadIdx.x;
    if (tid < HH) g_hidden[row*HH + tid] = nodes[row*HH + tid];

    const float4* e4 = (const float4*)edges + (size_t)row * NN;
    float4 e = e4[tid];
    float s = (e.x + e.y) + (e.z + e.w);
    __shared__ float red[128];
    red[tid] = s;
    __syncthreads();
    for (int off = 64; off > 0; off >>= 1) {
        if (tid < off) red[tid] += red[tid + off];
        __syncthreads();
    }
    if (tid == 0) g_nodemask[row] = (red[0] != 0.0f) ? 1 : 0;
}

// ---------------------------------------------------------------------------
// proj: hv = hidden @ Wv, hw = hidden @ Ww.
// 256 thr = 8 warps, 4 rows/warp -> 32 rows/block, grid = 128.
// lane -> h0 = lane*4 (padded to 128). Per k: 2 LDG.128 (weights, already
// f32x2-paired) + 4 broadcast LDS.64 (dup'd x) + 16 FMA2.
// ---------------------------------------------------------------------------
__global__ void __launch_bounds__(256)
k_proj() {
    __shared__ u64 sX[32*100];     // 25.6 KB, layout [r][k], value {x,x}
    int tid  = threadIdx.x;
    int base = blockIdx.x * 32;

    for (int i = tid; i < 32*100; i += 256) {
        int r = i / 100, k = i - r*100;
        sX[i] = pack2(g_hidden[(base + r)*HH + k]);
    }
    __syncthreads();

    int lane = tid & 31, warp = tid >> 5;
    int h0   = lane * 4;
    const float* pv = g_Wv_p + h0;
    const float* pw = g_Ww_p + h0;
    const u64* xw = sX + warp*4*100;

    u64 av[4][2], aw[4][2];
    #pragma unroll
    for (int r = 0; r < 4; r++) { av[r][0]=0; av[r][1]=0; aw[r][0]=0; aw[r][1]=0; }

    #pragma unroll 4
    for (int k = 0; k < 100; k++) {
        ulonglong2 wv2 = *(const ulonglong2*)(pv + k*HP);
        ulonglong2 ww2 = *(const ulonglong2*)(pw + k*HP);
        #pragma unroll
        for (int r = 0; r < 4; r++) {
            u64 x = xw[r*100 + k];
            av[r][0] = fma2(x, wv2.x, av[r][0]);
            av[r][1] = fma2(x, wv2.y, av[r][1]);
            aw[r][0] = fma2(x, ww2.x, aw[r][0]);
            aw[r][1] = fma2(x, ww2.y, aw[r][1]);
        }
    }

    #pragma unroll
    for (int r = 0; r < 4; r++) {
        int row = base + warp*4 + r;
        float fv[4], fw[4];
        unpack2(av[r][0], fv[0], fv[1]); unpack2(av[r][1], fv[2], fv[3]);
        unpack2(aw[r][0], fw[0], fw[1]); unpack2(aw[r][1], fw[2], fw[3]);
        #pragma unroll
        for (int j = 0; j < 4; j++) {
            if (h0 + j < HH) {
                g_hv[row*HH + h0 + j] = fv[j];
                g_hw[row*HH + h0 + j] = fw[j];
            }
        }
    }
}

// ---------------------------------------------------------------------------
// msg: messages[b,v,h] = sum_w [adj!=0] * relu(hv[v,h] + hw[w,h] + e.We)
// ---------------------------------------------------------------------------
__global__ void k_msg(const float* __restrict__ edges,
                      const float* __restrict__ We) {
    extern __shared__ float smem[];
    float*  s_hw  = smem;                        // 12800 floats
    float4* s_e   = (float4*)(smem + 12800);     // 512 float4
    float*  s_adj = smem + 12800 + 2048;         // 512 floats (0/1 mask)

    int bx  = blockIdx.x;
    int b   = bx >> 5;
    int v0  = (bx & 31) * 4;
    int tid = threadIdx.x;

    for (int i = tid; i < NN*HH; i += 512)
        s_hw[i] = g_hw[(b*NN)*HH + i];
    {
        int vloc = tid >> 7, w = tid & 127;
        const float4* e4 = (const float4*)edges;
        float4 e = e4[(size_t)((b*NN + v0 + vloc) * NN) + w];
        s_e[tid]   = e;
        float s = (e.x + e.y) + (e.z + e.w);
        s_adj[tid] = (s != 0.0f) ? 1.0f : 0.0f;
    }
    __syncthreads();

    int vloc = tid >> 7;
    int h    = tid & 127;
    if (h < HH) {
        float we0 = We[h], we1 = We[HH + h], we2 = We[2*HH + h], we3 = We[3*HH + h];
        float hvh = g_hv[(b*NN + v0 + vloc)*HH + h];
        const float4* ev = s_e   + (vloc << 7);
        const float*  av = s_adj + (vloc << 7);
        float acc0 = 0.f, acc1 = 0.f;
        #pragma unroll 4
        for (int w = 0; w < NN; w += 2) {
            float4 e0  = ev[w];
            float pre0 = hvh + s_hw[w*HH + h];
            pre0 = fmaf(e0.x, we0, pre0);
            pre0 = fmaf(e0.y, we1, pre0);
            pre0 = fmaf(e0.z, we2, pre0);
            pre0 = fmaf(e0.w, we3, pre0);
            acc0 = fmaf(fmaxf(pre0, 0.f), av[w], acc0);

            float4 e1  = ev[w + 1];
            float pre1 = hvh + s_hw[(w + 1)*HH + h];
            pre1 = fmaf(e1.x, we0, pre1);
            pre1 = fmaf(e1.y, we1, pre1);
            pre1 = fmaf(e1.z, we2, pre1);
            pre1 = fmaf(e1.w, we3, pre1);
            acc1 = fmaf(fmaxf(pre1, 0.f), av[w + 1], acc1);
        }
        g_msg[(b*NN + v0 + vloc)*HH + h] = acc0 + acc1;
    }
}

// ---------------------------------------------------------------------------
// update: hidden = node_mask ? tanh([hidden, msg] @ Wu) : hidden
// same mapping as k_proj; k = 200 ([hidden;msg]). dyn smem 51.2KB.
// Per k: 1 LDG.128 + 4 LDS.64 + 8 FMA2.
// ---------------------------------------------------------------------------
__global__ void __launch_bounds__(256)
k_update() {
    extern __shared__ u64 sXd[];   // [32][200], {x,x}
    int tid  = threadIdx.x;
    int base = blockIdx.x * 32;

    for (int i = tid; i < 32*200; i += 256) {
        int r = i / 200, k = i - r*200;
        float x = (k < HH) ? g_hidden[(base + r)*HH + k]
                           : g_msg   [(base + r)*HH + (k - HH)];
        sXd[i] = pack2(x);
    }
    __syncthreads();

    int lane = tid & 31, warp = tid >> 5;
    int h0   = lane * 4;
    const float* pu = g_Wu_p + h0;
    const u64* xw = sXd + warp*4*200;

    u64 a[4][2];
    #pragma unroll
    for (int r = 0; r < 4; r++) { a[r][0]=0; a[r][1]=0; }

    #pragma unroll 4
    for (int k = 0; k < 200; k++) {
        ulonglong2 w2 = *(const ulonglong2*)(pu + k*HP);
        #pragma unroll
        for (int r = 0; r < 4; r++) {
            u64 x = xw[r*200 + k];
            a[r][0] = fma2(x, w2.x, a[r][0]);
            a[r][1] = fma2(x, w2.y, a[r][1]);
        }
    }

    #pragma unroll
    for (int r = 0; r < 4; r++) {
        int row  = base + warp*4 + r;
        int mask = g_nodemask[row];
        float f[4];
        unpack2(a[r][0], f[0], f[1]); unpack2(a[r][1], f[2], f[3]);
        #pragma unroll
        for (int j = 0; j < 4; j++) {
            int h = h0 + j;
            if (h < HH) {
                float oldv, dummy;
                unpack2(xw[r*200 + h], oldv, dummy);  // staged hidden value
                g_hidden[row*HH + h] = mask ? tanhf(f[j]) : oldv;
            }
        }
    }
}

// ---------------------------------------------------------------------------
// readout: gterm = node_mask ? relu([hidden, nodes] @ Wr) : 0
// ---------------------------------------------------------------------------
__global__ void __launch_bounds__(256)
k_readout(const float* __restrict__ nodes) {
    extern __shared__ u64 sXd[];   // [32][200]
    int tid  = threadIdx.x;
    int base = blockIdx.x * 32;

    for (int i = tid; i < 32*200; i += 256) {
        int r = i / 200, k = i - r*200;
        float x = (k < HH) ? g_hidden[(base + r)*HH + k]
                           : nodes   [(base + r)*HH + (k - HH)];
        sXd[i] = pack2(x);
    }
    __syncthreads();

    int lane = tid & 31, warp = tid >> 5;
    int h0   = lane * 4;
    const float* pr = g_Wr_p + h0;
    const u64* xw = sXd + warp*4*200;

    u64 a[4][2];
    #pragma unroll
    for (int r = 0; r < 4; r++) { a[r][0]=0; a[r][1]=0; }

    #pragma unroll 4
    for (int k = 0; k < 200; k++) {
        ulonglong2 w2 = *(const ulonglong2*)(pr + k*HP);
        #pragma unroll
        for (int r = 0; r < 4; r++) {
            u64 x = xw[r*200 + k];
            a[r][0] = fma2(x, w2.x, a[r][0]);
            a[r][1] = fma2(x, w2.y, a[r][1]);
        }
    }

    #pragma unroll
    for (int r = 0; r < 4; r++) {
        int row  = base + warp*4 + r;
        float m  = g_nodemask[row] ? 1.f : 0.f;
        float f[4];
        unpack2(a[r][0], f[0], f[1]); unpack2(a[r][1], f[2], f[3]);
        #pragma unroll
        for (int j = 0; j < 4; j++) {
            if (h0 + j < HH)
                g_gterm[row*HH + h0 + j] = fmaxf(f[j], 0.f) * m;
        }
    }
}

// ---------------------------------------------------------------------------
// reduce: out[b,h] = sum_v gterm[b,v,h]  (deterministic, no atomics)
// ---------------------------------------------------------------------------
__global__ void k_reduce(float* __restrict__ out) {
    int b   = blockIdx.x;
    int tid = threadIdx.x;           // 512
    int q   = tid >> 7;
    int h   = tid & 127;
    __shared__ float red[4][128];
    float acc = 0.f;
    if (h < HH) {
        int v0 = q * 32;
        #pragma unroll 4
        for (int v = v0; v < v0 + 32; v++)
            acc += g_gterm[(b*NN + v)*HH + h];
    }
    red[q][h] = acc;
    __syncthreads();
    if (q == 0 && h < HH)
        out[b*HH + h] = (red[0][h] + red[1][h]) + (red[2][h] + red[3][h]);
}

extern "C" void kernel_launch(void* const* d_in, const int* in_sizes, int n_in,
                              void* d_out, int out_size) {
    const float* nodes = (const float*)d_in[0];
    const float* edges = (const float*)d_in[1];
    const float* Wv    = (const float*)d_in[2];
    const float* Ww    = (const float*)d_in[3];
    const float* We    = (const float*)d_in[4];
    const float* Wu    = (const float*)d_in[5];
    const float* Wr    = (const float*)d_in[6];
    float* out = (float*)d_out;

    cudaFuncSetAttribute(k_msg,     cudaFuncAttributeMaxDynamicSharedMemorySize, 61440);
    cudaFuncSetAttribute(k_update,  cudaFuncAttributeMaxDynamicSharedMemorySize, 51200);
    cudaFuncSetAttribute(k_readout, cudaFuncAttributeMaxDynamicSharedMemorySize, 51200);

    k_prep<<<300, 256>>>(Wv, Ww, Wu, Wr);
    k_init<<<ROWS, 128>>>(nodes, edges);
    for (int p = 0; p < 3; p++) {
        k_proj<<<ROWS/32, 256>>>();
        k_msg<<<1024, 512, 61440>>>(edges, We);
        k_update<<<ROWS/32, 256, 51200>>>();
    }
    k_readout<<<ROWS/32, 256, 51200>>>(nodes);
    k_reduce<<<BB, 512>>>(out);
}

// round 6
// speedup vs baseline: 1.0267x; 1.0267x over previous
#include <cuda_runtime.h>

#define BB 32
#define NN 128
#define HH 100
#define HP 128          // padded h
#define ROWS (BB*NN)    // 4096

// Scratch (static device allocations — allowed)
__device__ float g_hidden[ROWS*HH];
__device__ float g_hv[ROWS*HH];
__device__ float g_hw[ROWS*HH];
__device__ float g_msg[ROWS*HH];
__device__ float g_gterm[ROWS*HH];
__device__ int   g_nodemask[ROWS];
// padded weights: [k][128], zeros for h >= 100
__device__ float g_Wv_p[100*HP];
__device__ float g_Ww_p[100*HP];
__device__ float g_Wu_p[200*HP];
__device__ float g_Wr_p[200*HP];

typedef unsigned long long u64;

__device__ __forceinline__ u64 fma2(u64 a, u64 b, u64 c) {
    u64 d;
    asm("fma.rn.f32x2 %0, %1, %2, %3;" : "=l"(d) : "l"(a), "l"(b), "l"(c));
    return d;
}
__device__ __forceinline__ u64 pack2(float w) {
    u64 d;
    asm("mov.b64 %0, {%1, %1};" : "=l"(d) : "f"(w));
    return d;
}
__device__ __forceinline__ void unpack2(u64 v, float& lo, float& hi) {
    asm("mov.b64 {%0, %1}, %2;" : "=f"(lo), "=f"(hi) : "l"(v));
}

// ---------------------------------------------------------------------------
// prep: pad weights to [k][128] with zero columns for h in [100,128)
// ---------------------------------------------------------------------------
__global__ void k_prep(const float* __restrict__ Wv, const float* __restrict__ Ww,
                       const float* __restrict__ Wu, const float* __restrict__ Wr) {
    int i = blockIdx.x * 256 + threadIdx.x;
    if (i < 12800) {
        int k = i >> 7, h = i & 127;
        g_Wv_p[i] = (h < HH) ? Wv[k*HH + h] : 0.f;
    } else if (i < 25600) {
        int j = i - 12800; int k = j >> 7, h = j & 127;
        g_Ww_p[j] = (h < HH) ? Ww[k*HH + h] : 0.f;
    } else if (i < 51200) {
        int j = i - 25600; int k = j >> 7, h = j & 127;
        g_Wu_p[j] = (h < HH) ? Wu[k*HH + h] : 0.f;
    } else if (i < 76800) {
        int j = i - 51200; int k = j >> 7, h = j & 127;
        g_Wr_p[j] = (h < HH) ? Wr[k*HH + h] : 0.f;
    }
}

// ---------------------------------------------------------------------------
// init: hidden = nodes; node_mask[row] = (sum_w sum_e edges[row,w,e]) != 0
// ---------------------------------------------------------------------------
__global__ void k_init(const float* __restrict__ nodes,
                       const float* __restrict__ edges) {
    int row = blockIdx.x;
    int tid = threadIdx.x;
    if (tid < HH) g_hidden[row*HH + tid] = nodes[row*HH + tid];

    const float4* e4 = (const float4*)edges + (size_t)row * NN;
    float4 e = e4[tid];
    float s = (e.x + e.y) + (e.z + e.w);
    __shared__ float red[128];
    red[tid] = s;
    __syncthreads();
    for (int off = 64; off > 0; off >>= 1) {
        if (tid < off) red[tid] += red[tid + off];
        __syncthreads();
    }
    if (tid == 0) g_nodemask[row] = (red[0] != 0.0f) ? 1 : 0;
}

// ---------------------------------------------------------------------------
// proj: hv = hidden @ Wv, hw = hidden @ Ww.
// 256 thr = 8 warps, 2 rows/warp -> 16 rows/block, grid = 256 (~2 blocks/SM,
// 16 warps/SM). lane -> h0 = lane*4. Per k: 2 LDG.128 (padded weights,
// f32x2-paired, L1-reused by all warps) + 2 broadcast LDS.64 + 8 FMA2.
// ---------------------------------------------------------------------------
__global__ void __launch_bounds__(256)
k_proj() {
    __shared__ u64 sX[16*100];     // 12.8 KB, [r][k], value {x,x}
    int tid  = threadIdx.x;
    int base = blockIdx.x * 16;

    for (int i = tid; i < 16*100; i += 256) {
        int r = i / 100, k = i - r*100;
        sX[i] = pack2(g_hidden[(base + r)*HH + k]);
    }
    __syncthreads();

    int lane = tid & 31, warp = tid >> 5;
    int h0   = lane * 4;
    const float* pv = g_Wv_p + h0;
    const float* pw = g_Ww_p + h0;
    const u64* x0 = sX + (warp*2    )*100;
    const u64* x1 = sX + (warp*2 + 1)*100;

    u64 av0a=0, av0b=0, av1a=0, av1b=0;
    u64 aw0a=0, aw0b=0, aw1a=0, aw1b=0;

    #pragma unroll 2
    for (int k = 0; k < 100; k++) {
        ulonglong2 wv2 = *(const ulonglong2*)(pv + k*HP);
        ulonglong2 ww2 = *(const ulonglong2*)(pw + k*HP);
        u64 xa = x0[k], xb = x1[k];
        av0a = fma2(xa, wv2.x, av0a); av0b = fma2(xa, wv2.y, av0b);
        av1a = fma2(xb, wv2.x, av1a); av1b = fma2(xb, wv2.y, av1b);
        aw0a = fma2(xa, ww2.x, aw0a); aw0b = fma2(xa, ww2.y, aw0b);
        aw1a = fma2(xb, ww2.x, aw1a); aw1b = fma2(xb, ww2.y, aw1b);
    }

    if (h0 <= 96) {   // lanes 0..24 cover h0..h0+3 < 100
        int row0 = base + warp*2;
        float4 v0, v1, w0, w1;
        unpack2(av0a, v0.x, v0.y); unpack2(av0b, v0.z, v0.w);
        unpack2(av1a, v1.x, v1.y); unpack2(av1b, v1.z, v1.w);
        unpack2(aw0a, w0.x, w0.y); unpack2(aw0b, w0.z, w0.w);
        unpack2(aw1a, w1.x, w1.y); unpack2(aw1b, w1.z, w1.w);
        *(float4*)(g_hv + (size_t)row0*HH + h0)       = v0;
        *(float4*)(g_hv + (size_t)(row0+1)*HH + h0)   = v1;
        *(float4*)(g_hw + (size_t)row0*HH + h0)       = w0;
        *(float4*)(g_hw + (size_t)(row0+1)*HH + h0)   = w1;
    }
}

// ---------------------------------------------------------------------------
// msg: messages[b,v,h] = sum_w [adj!=0] * relu(hv[v,h] + hw[w,h] + e.We)
// (unchanged — isolate the GEMM fix this round)
// ---------------------------------------------------------------------------
__global__ void k_msg(const float* __restrict__ edges,
                      const float* __restrict__ We) {
    extern __shared__ float smem[];
    float*  s_hw  = smem;                        // 12800 floats
    float4* s_e   = (float4*)(smem + 12800);     // 512 float4
    float*  s_adj = smem + 12800 + 2048;         // 512 floats (0/1 mask)

    int bx  = blockIdx.x;
    int b   = bx >> 5;
    int v0  = (bx & 31) * 4;
    int tid = threadIdx.x;

    for (int i = tid; i < NN*HH; i += 512)
        s_hw[i] = g_hw[(b*NN)*HH + i];
    {
        int vloc = tid >> 7, w = tid & 127;
        const float4* e4 = (const float4*)edges;
        float4 e = e4[(size_t)((b*NN + v0 + vloc) * NN) + w];
        s_e[tid]   = e;
        float s = (e.x + e.y) + (e.z + e.w);
        s_adj[tid] = (s != 0.0f) ? 1.0f : 0.0f;
    }
    __syncthreads();

    int vloc = tid >> 7;
    int h    = tid & 127;
    if (h < HH) {
        float we0 = We[h], we1 = We[HH + h], we2 = We[2*HH + h], we3 = We[3*HH + h];
        float hvh = g_hv[(b*NN + v0 + vloc)*HH + h];
        const float4* ev = s_e   + (vloc << 7);
        const float*  av = s_adj + (vloc << 7);
        float acc0 = 0.f, acc1 = 0.f;
        #pragma unroll 4
        for (int w = 0; w < NN; w += 2) {
            float4 e0  = ev[w];
            float pre0 = hvh + s_hw[w*HH + h];
            pre0 = fmaf(e0.x, we0, pre0);
            pre0 = fmaf(e0.y, we1, pre0);
            pre0 = fmaf(e0.z, we2, pre0);
            pre0 = fmaf(e0.w, we3, pre0);
            acc0 = fmaf(fmaxf(pre0, 0.f), av[w], acc0);

            float4 e1  = ev[w + 1];
            float pre1 = hvh + s_hw[(w + 1)*HH + h];
            pre1 = fmaf(e1.x, we0, pre1);
            pre1 = fmaf(e1.y, we1, pre1);
            pre1 = fmaf(e1.z, we2, pre1);
            pre1 = fmaf(e1.w, we3, pre1);
            acc1 = fmaf(fmaxf(pre1, 0.f), av[w + 1], acc1);
        }
        g_msg[(b*NN + v0 + vloc)*HH + h] = acc0 + acc1;
    }
}

// ---------------------------------------------------------------------------
// update: hidden = node_mask ? tanh([hidden, msg] @ Wu) : hidden
// 2 rows/warp, 16 rows/block, grid 256. Per k: 1 LDG.128 + 2 LDS.64 + 4 FMA2.
// ---------------------------------------------------------------------------
__global__ void __launch_bounds__(256)
k_update() {
    __shared__ u64 sX[16*200];     // 25.6 KB
    int tid  = threadIdx.x;
    int base = blockIdx.x * 16;

    for (int i = tid; i < 16*200; i += 256) {
        int r = i / 200, k = i - r*200;
        float x = (k < HH) ? g_hidden[(base + r)*HH + k]
                           : g_msg   [(base + r)*HH + (k - HH)];
        sX[i] = pack2(x);
    }
    __syncthreads();

    int lane = tid & 31, warp = tid >> 5;
    int h0   = lane * 4;
    const float* pu = g_Wu_p + h0;
    const u64* x0 = sX + (warp*2    )*200;
    const u64* x1 = sX + (warp*2 + 1)*200;

    u64 a0a=0, a0b=0, a1a=0, a1b=0;

    #pragma unroll 4
    for (int k = 0; k < 200; k++) {
        ulonglong2 w2 = *(const ulonglong2*)(pu + k*HP);
        u64 xa = x0[k], xb = x1[k];
        a0a = fma2(xa, w2.x, a0a); a0b = fma2(xa, w2.y, a0b);
        a1a = fma2(xb, w2.x, a1a); a1b = fma2(xb, w2.y, a1b);
    }

    if (h0 <= 96) {
        int row0 = base + warp*2;
        float4 f0, f1;
        unpack2(a0a, f0.x, f0.y); unpack2(a0b, f0.z, f0.w);
        unpack2(a1a, f1.x, f1.y); unpack2(a1b, f1.z, f1.w);
        int m0 = g_nodemask[row0], m1 = g_nodemask[row0 + 1];
        float4 o0, o1;   // old hidden from staged x (low half of dup)
        {
            float d;
            unpack2(x0[h0],   o0.x, d); unpack2(x0[h0+1], o0.y, d);
            unpack2(x0[h0+2], o0.z, d); unpack2(x0[h0+3], o0.w, d);
            unpack2(x1[h0],   o1.x, d); unpack2(x1[h0+1], o1.y, d);
            unpack2(x1[h0+2], o1.z, d); unpack2(x1[h0+3], o1.w, d);
        }
        float4 r0, r1;
        r0.x = m0 ? tanhf(f0.x) : o0.x; r0.y = m0 ? tanhf(f0.y) : o0.y;
        r0.z = m0 ? tanhf(f0.z) : o0.z; r0.w = m0 ? tanhf(f0.w) : o0.w;
        r1.x = m1 ? tanhf(f1.x) : o1.x; r1.y = m1 ? tanhf(f1.y) : o1.y;
        r1.z = m1 ? tanhf(f1.z) : o1.z; r1.w = m1 ? tanhf(f1.w) : o1.w;
        *(float4*)(g_hidden + (size_t)row0*HH + h0)     = r0;
        *(float4*)(g_hidden + (size_t)(row0+1)*HH + h0) = r1;
    }
}

// ---------------------------------------------------------------------------
// readout: gterm = node_mask ? relu([hidden, nodes] @ Wr) : 0
// ---------------------------------------------------------------------------
__global__ void __launch_bounds__(256)
k_readout(const float* __restrict__ nodes) {
    __shared__ u64 sX[16*200];
    int tid  = threadIdx.x;
    int base = blockIdx.x * 16;

    for (int i = tid; i < 16*200; i += 256) {
        int r = i / 200, k = i - r*200;
        float x = (k < HH) ? g_hidden[(base + r)*HH + k]
                           : nodes   [(base + r)*HH + (k - HH)];
        sX[i] = pack2(x);
    }
    __syncthreads();

    int lane = tid & 31, warp = tid >> 5;
    int h0   = lane * 4;
    const float* pr = g_Wr_p + h0;
    const u64* x0 = sX + (warp*2    )*200;
    const u64* x1 = sX + (warp*2 + 1)*200;

    u64 a0a=0, a0b=0, a1a=0, a1b=0;

    #pragma unroll 4
    for (int k = 0; k < 200; k++) {
        ulonglong2 w2 = *(const ulonglong2*)(pr + k*HP);
        u64 xa = x0[k], xb = x1[k];
        a0a = fma2(xa, w2.x, a0a); a0b = fma2(xa, w2.y, a0b);
        a1a = fma2(xb, w2.x, a1a); a1b = fma2(xb, w2.y, a1b);
    }

    if (h0 <= 96) {
        int row0 = base + warp*2;
        float m0 = g_nodemask[row0]     ? 1.f : 0.f;
        float m1 = g_nodemask[row0 + 1] ? 1.f : 0.f;
        float4 f0, f1;
        unpack2(a0a, f0.x, f0.y); unpack2(a0b, f0.z, f0.w);
        unpack2(a1a, f1.x, f1.y); unpack2(a1b, f1.z, f1.w);
        float4 r0, r1;
        r0.x = fmaxf(f0.x, 0.f)*m0; r0.y = fmaxf(f0.y, 0.f)*m0;
        r0.z = fmaxf(f0.z, 0.f)*m0; r0.w = fmaxf(f0.w, 0.f)*m0;
        r1.x = fmaxf(f1.x, 0.f)*m1; r1.y = fmaxf(f1.y, 0.f)*m1;
        r1.z = fmaxf(f1.z, 0.f)*m1; r1.w = fmaxf(f1.w, 0.f)*m1;
        *(float4*)(g_gterm + (size_t)row0*HH + h0)     = r0;
        *(float4*)(g_gterm + (size_t)(row0+1)*HH + h0) = r1;
    }
}

// ---------------------------------------------------------------------------
// reduce: out[b,h] = sum_v gterm[b,v,h]  (deterministic, no atomics)
// ---------------------------------------------------------------------------
__global__ void k_reduce(float* __restrict__ out) {
    int b   = blockIdx.x;
    int tid = threadIdx.x;           // 512
    int q   = tid >> 7;
    int h   = tid & 127;
    __shared__ float red[4][128];
    float acc = 0.f;
    if (h < HH) {
        int v0 = q * 32;
        #pragma unroll 4
        for (int v = v0; v < v0 + 32; v++)
            acc += g_gterm[(b*NN + v)*HH + h];
    }
    red[q][h] = acc;
    __syncthreads();
    if (q == 0 && h < HH)
        out[b*HH + h] = (red[0][h] + red[1][h]) + (red[2][h] + red[3][h]);
}

extern "C" void kernel_launch(void* const* d_in, const int* in_sizes, int n_in,
                              void* d_out, int out_size) {
    const float* nodes = (const float*)d_in[0];
    const float* edges = (const float*)d_in[1];
    const float* Wv    = (const float*)d_in[2];
    const float* Ww    = (const float*)d_in[3];
    const float* We    = (const float*)d_in[4];
    const float* Wu    = (const float*)d_in[5];
    const float* Wr    = (const float*)d_in[6];
    float* out = (float*)d_out;

    cudaFuncSetAttribute(k_msg, cudaFuncAttributeMaxDynamicSharedMemorySize, 61440);

    k_prep<<<300, 256>>>(Wv, Ww, Wu, Wr);
    k_init<<<ROWS, 128>>>(nodes, edges);
    for (int p = 0; p < 3; p++) {
        k_proj<<<ROWS/16, 256>>>();
        k_msg<<<1024, 512, 61440>>>(edges, We);
        k_update<<<ROWS/16, 256>>>();
    }
    k_readout<<<ROWS/16, 256>>>(nodes);
    k_reduce<<<BB, 512>>>(out);
}

// round 7
// speedup vs baseline: 1.4639x; 1.4259x over previous
#include <cuda_runtime.h>

#define BB 32
#define NN 128
#define HH 100
#define ROWS (BB*NN)    // 4096

// Scratch (static device allocations — allowed)
__device__ float g_hidden[ROWS*HH];
__device__ float g_hv[ROWS*HH];
__device__ float g_hw[ROWS*HH];
__device__ float g_msg[ROWS*HH];
__device__ float g_gterm[ROWS*HH];
__device__ int   g_nodemask[ROWS];

typedef unsigned long long u64;

__device__ __forceinline__ u64 fma2(u64 a, u64 b, u64 c) {
    u64 d;
    asm("fma.rn.f32x2 %0, %1, %2, %3;" : "=l"(d) : "l"(a), "l"(b), "l"(c));
    return d;
}
__device__ __forceinline__ u64 add2(u64 a, u64 b) {
    u64 d;
    asm("add.rn.f32x2 %0, %1, %2;" : "=l"(d) : "l"(a), "l"(b));
    return d;
}
__device__ __forceinline__ u64 pack2(float w) {
    u64 d;
    asm("mov.b64 %0, {%1, %1};" : "=l"(d) : "f"(w));
    return d;
}
__device__ __forceinline__ u64 packlh(float lo, float hi) {
    u64 d;
    asm("mov.b64 %0, {%1, %2};" : "=l"(d) : "f"(lo), "f"(hi));
    return d;
}
__device__ __forceinline__ void unpack2(u64 v, float& lo, float& hi) {
    asm("mov.b64 {%0, %1}, %2;" : "=f"(lo), "=f"(hi) : "l"(v));
}

// ---------------------------------------------------------------------------
// init + mask + proj of pass 1. Block = 4 rows, 128 threads, grid 1024.
// ---------------------------------------------------------------------------
__global__ void __launch_bounds__(128)
k_init_proj(const float* __restrict__ nodes, const float* __restrict__ edges,
            const float* __restrict__ Wv, const float* __restrict__ Ww) {
    __shared__ float4 sP[HH];        // nodes transposed: sP[k] = rows 0..3
    int base = blockIdx.x * 4;
    int tid  = threadIdx.x;

    // node mask: one warp per row, 4 float4 each lane
    {
        int r = tid >> 5, lane = tid & 31;
        const float4* e4 = (const float4*)edges + (size_t)(base + r) * NN;
        float s = 0.f;
        #pragma unroll
        for (int j = 0; j < 4; j++) {
            float4 e = e4[lane + 32*j];
            s += (e.x + e.y) + (e.z + e.w);
        }
        #pragma unroll
        for (int off = 16; off > 0; off >>= 1)
            s += __shfl_xor_sync(0xffffffffu, s, off);
        if (lane == 0) g_nodemask[base + r] = (s != 0.0f) ? 1 : 0;
    }

    if (tid < HH) {
        int h = tid;
        float x0 = nodes[(size_t)(base+0)*HH + h];
        float x1 = nodes[(size_t)(base+1)*HH + h];
        float x2 = nodes[(size_t)(base+2)*HH + h];
        float x3 = nodes[(size_t)(base+3)*HH + h];
        g_hidden[(size_t)(base+0)*HH + h] = x0;
        g_hidden[(size_t)(base+1)*HH + h] = x1;
        g_hidden[(size_t)(base+2)*HH + h] = x2;
        g_hidden[(size_t)(base+3)*HH + h] = x3;
        sP[h] = make_float4(x0, x1, x2, x3);
    }
    __syncthreads();

    if (tid < HH) {
        int h = tid;
        const ulonglong2* sP2 = (const ulonglong2*)sP;
        u64 v01=0, v23=0, w01=0, w23=0;
        #pragma unroll 4
        for (int k = 0; k < HH; k++) {
            ulonglong2 x = sP2[k];
            u64 wv = pack2(Wv[k*HH + h]);
            u64 ww = pack2(Ww[k*HH + h]);
            v01 = fma2(x.x, wv, v01); v23 = fma2(x.y, wv, v23);
            w01 = fma2(x.x, ww, w01); w23 = fma2(x.y, ww, w23);
        }
        float a,b,c,d, e,f,g,q;
        unpack2(v01, a, b); unpack2(v23, c, d);
        unpack2(w01, e, f); unpack2(w23, g, q);
        g_hv[(size_t)(base+0)*HH + h] = a;
        g_hv[(size_t)(base+1)*HH + h] = b;
        g_hv[(size_t)(base+2)*HH + h] = c;
        g_hv[(size_t)(base+3)*HH + h] = d;
        g_hw[(size_t)(base+0)*HH + h] = e;
        g_hw[(size_t)(base+1)*HH + h] = f;
        g_hw[(size_t)(base+2)*HH + h] = g;
        g_hw[(size_t)(base+3)*HH + h] = q;
    }
}

// ---------------------------------------------------------------------------
// msg: f32x2 over h-pairs. Block = 8 v-rows of one batch, 512 threads,
// grid = 512. Shared: hw pairs (51200B) + pre-dup'd edge packs (32768B)
// + dup'd masks (8192B) = 92160B dynamic.
// thread = (vloc = tid/64, p = tid%64), h0 = 2p, p < 50 active.
// ---------------------------------------------------------------------------
__global__ void __launch_bounds__(512)
k_msg(const float* __restrict__ edges, const float* __restrict__ We) {
    extern __shared__ u64 sm[];
    u64* s_hw2 = sm;                  // [w*50 + p], genuine {h,h+1} pairs
    u64* s_e2  = sm + 6400;           // [(v*128+w)*4 + j], dup'd {e,e}
    u64* s_m2  = sm + 6400 + 4096;    // [v*128+w], dup'd {m,m}

    int bx  = blockIdx.x;
    int b   = bx >> 4;
    int v0  = (bx & 15) * 8;
    int tid = threadIdx.x;
    int bN  = b * NN;

    for (int i = tid; i < 128*50; i += 512) {
        int w = i / 50, p = i - w*50;
        s_hw2[i] = *(const u64*)(g_hw + (size_t)(bN + w)*HH + 2*p);
    }
    for (int j = tid; j < 1024; j += 512) {
        int v = j >> 7, w = j & 127;
        float4 e = ((const float4*)edges)[(size_t)(bN + v0 + v)*NN + w];
        u64* dst = s_e2 + j*4;
        dst[0] = pack2(e.x); dst[1] = pack2(e.y);
        dst[2] = pack2(e.z); dst[3] = pack2(e.w);
        float s = (e.x + e.y) + (e.z + e.w);
        s_m2[j] = pack2((s != 0.0f) ? 1.0f : 0.0f);
    }
    __syncthreads();

    int vloc = tid >> 6;
    int p    = tid & 63;
    if (p < 50) {
        int h0  = 2*p;
        int row = bN + v0 + vloc;
        u64 hv2 = *(const u64*)(g_hv + (size_t)row*HH + h0);
        u64 we0 = *(const u64*)(We + h0);
        u64 we1 = *(const u64*)(We + HH + h0);
        u64 we2 = *(const u64*)(We + 2*HH + h0);
        u64 we3 = *(const u64*)(We + 3*HH + h0);
        const u64* ev  = s_e2 + vloc*512;
        const u64* mv  = s_m2 + vloc*128;
        const u64* hwp = s_hw2 + p;
        u64 acc = 0;
        #pragma unroll 2
        for (int w = 0; w < NN; w++) {
            ulonglong2 e01 = *(const ulonglong2*)(ev + w*4);
            ulonglong2 e23 = *(const ulonglong2*)(ev + w*4 + 2);
            u64 pre = add2(hv2, hwp[w*50]);
            pre = fma2(e01.x, we0, pre);
            pre = fma2(e01.y, we1, pre);
            pre = fma2(e23.x, we2, pre);
            pre = fma2(e23.y, we3, pre);
            float lo, hi; unpack2(pre, lo, hi);
            lo = fmaxf(lo, 0.f); hi = fmaxf(hi, 0.f);
            acc = fma2(packlh(lo, hi), mv[w], acc);
        }
        float a0, a1; unpack2(acc, a0, a1);
        *(float2*)(g_msg + (size_t)row*HH + h0) = make_float2(a0, a1);
    }
}

// ---------------------------------------------------------------------------
// update (masked tanh) fused with proj of the NEW hidden. 4 rows, 128 thr,
// grid 1024. Inner update: 1 LDS.128 + 1 LDG + 1 pack + 2 fma2 per k.
// ---------------------------------------------------------------------------
__global__ void __launch_bounds__(128)
k_updproj(const float* __restrict__ Wu, const float* __restrict__ Wv,
          const float* __restrict__ Ww) {
    __shared__ float4 sU[2*HH];      // [hidden; msg] transposed
    __shared__ float4 sP[HH];        // new hidden transposed
    int base = blockIdx.x * 4;
    int tid  = threadIdx.x;
    float* sUf = (float*)sU;

    for (int i = tid; i < 4*2*HH; i += 128) {
        int r = i / (2*HH), k = i - r*(2*HH);
        float x = (k < HH) ? g_hidden[(size_t)(base + r)*HH + k]
                           : g_msg   [(size_t)(base + r)*HH + (k - HH)];
        sUf[k*4 + r] = x;
    }
    __syncthreads();

    if (tid < HH) {
        int h = tid;
        const ulonglong2* sU2 = (const ulonglong2*)sU;
        u64 a01=0, a23=0;
        #pragma unroll 4
        for (int k = 0; k < 2*HH; k++) {
            ulonglong2 x = sU2[k];
            u64 w = pack2(Wu[k*HH + h]);
            a01 = fma2(x.x, w, a01);
            a23 = fma2(x.y, w, a23);
        }
        float f0,f1,f2,f3;
        unpack2(a01, f0, f1); unpack2(a23, f2, f3);
        float n0 = g_nodemask[base+0] ? tanhf(f0) : sUf[h*4+0];
        float n1 = g_nodemask[base+1] ? tanhf(f1) : sUf[h*4+1];
        float n2 = g_nodemask[base+2] ? tanhf(f2) : sUf[h*4+2];
        float n3 = g_nodemask[base+3] ? tanhf(f3) : sUf[h*4+3];
        g_hidden[(size_t)(base+0)*HH + h] = n0;
        g_hidden[(size_t)(base+1)*HH + h] = n1;
        g_hidden[(size_t)(base+2)*HH + h] = n2;
        g_hidden[(size_t)(base+3)*HH + h] = n3;
        sP[h] = make_float4(n0, n1, n2, n3);
    }
    __syncthreads();

    if (tid < HH) {
        int h = tid;
        const ulonglong2* sP2 = (const ulonglong2*)sP;
        u64 v01=0, v23=0, w01=0, w23=0;
        #pragma unroll 4
        for (int k = 0; k < HH; k++) {
            ulonglong2 x = sP2[k];
            u64 wv = pack2(Wv[k*HH + h]);
            u64 ww = pack2(Ww[k*HH + h]);
            v01 = fma2(x.x, wv, v01); v23 = fma2(x.y, wv, v23);
            w01 = fma2(x.x, ww, w01); w23 = fma2(x.y, ww, w23);
        }
        float a,b,c,d, e,f,g,q;
        unpack2(v01, a, b); unpack2(v23, c, d);
        unpack2(w01, e, f); unpack2(w23, g, q);
        g_hv[(size_t)(base+0)*HH + h] = a;
        g_hv[(size_t)(base+1)*HH + h] = b;
        g_hv[(size_t)(base+2)*HH + h] = c;
        g_hv[(size_t)(base+3)*HH + h] = d;
        g_hw[(size_t)(base+0)*HH + h] = e;
        g_hw[(size_t)(base+1)*HH + h] = f;
        g_hw[(size_t)(base+2)*HH + h] = g;
        g_hw[(size_t)(base+3)*HH + h] = q;
    }
}

// ---------------------------------------------------------------------------
// final update fused with readout gterm. No g_hidden write needed.
// ---------------------------------------------------------------------------
__global__ void __launch_bounds__(128)
k_updread(const float* __restrict__ nodes, const float* __restrict__ Wu,
          const float* __restrict__ Wr) {
    __shared__ float4 sU[2*HH];      // [hidden; msg]
    __shared__ float4 sR[2*HH];      // [new_hidden; nodes]
    int base = blockIdx.x * 4;
    int tid  = threadIdx.x;
    float* sUf = (float*)sU;
    float* sRf = (float*)sR;

    for (int i = tid; i < 4*2*HH; i += 128) {
        int r = i / (2*HH), k = i - r*(2*HH);
        float x = (k < HH) ? g_hidden[(size_t)(base + r)*HH + k]
                           : g_msg   [(size_t)(base + r)*HH + (k - HH)];
        sUf[k*4 + r] = x;
    }
    for (int i = tid; i < 4*HH; i += 128) {
        int r = i / HH, k = i - r*HH;
        sRf[(HH + k)*4 + r] = nodes[(size_t)(base + r)*HH + k];
    }
    __syncthreads();

    if (tid < HH) {
        int h = tid;
        const ulonglong2* sU2 = (const ulonglong2*)sU;
        u64 a01=0, a23=0;
        #pragma unroll 4
        for (int k = 0; k < 2*HH; k++) {
            ulonglong2 x = sU2[k];
            u64 w = pack2(Wu[k*HH + h]);
            a01 = fma2(x.x, w, a01);
            a23 = fma2(x.y, w, a23);
        }
        float f0,f1,f2,f3;
        unpack2(a01, f0, f1); unpack2(a23, f2, f3);
        float n0 = g_nodemask[base+0] ? tanhf(f0) : sUf[h*4+0];
        float n1 = g_nodemask[base+1] ? tanhf(f1) : sUf[h*4+1];
        float n2 = g_nodemask[base+2] ? tanhf(f2) : sUf[h*4+2];
        float n3 = g_nodemask[base+3] ? tanhf(f3) : sUf[h*4+3];
        sR[h] = make_float4(n0, n1, n2, n3);
    }
    __syncthreads();

    if (tid < HH) {
        int h = tid;
        const ulonglong2* sR2 = (const ulonglong2*)sR;
        u64 a01=0, a23=0;
        #pragma unroll 4
        for (int k = 0; k < 2*HH; k++) {
            ulonglong2 x = sR2[k];
            u64 w = pack2(Wr[k*HH + h]);
            a01 = fma2(x.x, w, a01);
            a23 = fma2(x.y, w, a23);
        }
        float f0,f1,f2,f3;
        unpack2(a01, f0, f1); unpack2(a23, f2, f3);
        float m0 = g_nodemask[base+0] ? 1.f : 0.f;
        float m1 = g_nodemask[base+1] ? 1.f : 0.f;
        float m2 = g_nodemask[base+2] ? 1.f : 0.f;
        float m3 = g_nodemask[base+3] ? 1.f : 0.f;
        g_gterm[(size_t)(base+0)*HH + h] = fmaxf(f0, 0.f) * m0;
        g_gterm[(size_t)(base+1)*HH + h] = fmaxf(f1, 0.f) * m1;
        g_gterm[(size_t)(base+2)*HH + h] = fmaxf(f2, 0.f) * m2;
        g_gterm[(size_t)(base+3)*HH + h] = fmaxf(f3, 0.f) * m3;
    }
}

// ---------------------------------------------------------------------------
// reduce: out[b,h] = sum_v gterm[b,v,h]  (deterministic, no atomics)
// ---------------------------------------------------------------------------
__global__ void k_reduce(float* __restrict__ out) {
    int b   = blockIdx.x;
    int tid = threadIdx.x;           // 512
    int q   = tid >> 7;
    int h   = tid & 127;
    __shared__ float red[4][128];
    float acc = 0.f;
    if (h < HH) {
        int v0 = q * 32;
        #pragma unroll 4
        for (int v = v0; v < v0 + 32; v++)
            acc += g_gterm[(size_t)(b*NN + v)*HH + h];
    }
    red[q][h] = acc;
    __syncthreads();
    if (q == 0 && h < HH)
        out[b*HH + h] = (red[0][h] + red[1][h]) + (red[2][h] + red[3][h]);
}

extern "C" void kernel_launch(void* const* d_in, const int* in_sizes, int n_in,
                              void* d_out, int out_size) {
    const float* nodes = (const float*)d_in[0];
    const float* edges = (const float*)d_in[1];
    const float* Wv    = (const float*)d_in[2];
    const float* Ww    = (const float*)d_in[3];
    const float* We    = (const float*)d_in[4];
    const float* Wu    = (const float*)d_in[5];
    const float* Wr    = (const float*)d_in[6];
    float* out = (float*)d_out;

    cudaFuncSetAttribute(k_msg, cudaFuncAttributeMaxDynamicSharedMemorySize, 92160);

    k_init_proj<<<ROWS/4, 128>>>(nodes, edges, Wv, Ww);
    for (int p = 0; p < 2; p++) {
        k_msg<<<512, 512, 92160>>>(edges, We);
        k_updproj<<<ROWS/4, 128>>>(Wu, Wv, Ww);
    }
    k_msg<<<512, 512, 92160>>>(edges, We);
    k_updread<<<ROWS/4, 128>>>(nodes, Wu, Wr);
    k_reduce<<<BB, 512>>>(out);
}

// round 8
// speedup vs baseline: 1.6904x; 1.1547x over previous
#include <cuda_runtime.h>

#define BB 32
#define NN 128
#define HH 100
#define ROWS (BB*NN)    // 4096

// Scratch (static device allocations — allowed)
__device__ float g_hidden[ROWS*HH];
__device__ float g_hv[ROWS*HH];
__device__ float g_hw[ROWS*HH];
__device__ float g_msg[ROWS*HH];
__device__ float g_gterm[ROWS*HH];
__device__ int   g_nodemask[ROWS];

typedef unsigned long long u64;

__device__ __forceinline__ u64 fma2(u64 a, u64 b, u64 c) {
    u64 d;
    asm("fma.rn.f32x2 %0, %1, %2, %3;" : "=l"(d) : "l"(a), "l"(b), "l"(c));
    return d;
}
__device__ __forceinline__ u64 add2(u64 a, u64 b) {
    u64 d;
    asm("add.rn.f32x2 %0, %1, %2;" : "=l"(d) : "l"(a), "l"(b));
    return d;
}
__device__ __forceinline__ u64 pack2(float w) {
    u64 d;
    asm("mov.b64 %0, {%1, %1};" : "=l"(d) : "f"(w));
    return d;
}
__device__ __forceinline__ u64 packlh(float lo, float hi) {
    u64 d;
    asm("mov.b64 %0, {%1, %2};" : "=l"(d) : "f"(lo), "f"(hi));
    return d;
}
__device__ __forceinline__ void unpack2(u64 v, float& lo, float& hi) {
    asm("mov.b64 {%0, %1}, %2;" : "=f"(lo), "=f"(hi) : "l"(v));
}
__device__ __forceinline__ u64 relu2(u64 v) {
    float lo, hi;
    unpack2(v, lo, hi);
    return packlh(fmaxf(lo, 0.f), fmaxf(hi, 0.f));
}

// ---------------------------------------------------------------------------
// init + mask + proj of pass 1. Block = 4 rows, 128 threads, grid 1024.
// ---------------------------------------------------------------------------
__global__ void __launch_bounds__(128)
k_init_proj(const float* __restrict__ nodes, const float* __restrict__ edges,
            const float* __restrict__ Wv, const float* __restrict__ Ww) {
    __shared__ float4 sP[HH];        // nodes transposed: sP[k] = rows 0..3
    int base = blockIdx.x * 4;
    int tid  = threadIdx.x;

    {
        int r = tid >> 5, lane = tid & 31;
        const float4* e4 = (const float4*)edges + (size_t)(base + r) * NN;
        float s = 0.f;
        #pragma unroll
        for (int j = 0; j < 4; j++) {
            float4 e = e4[lane + 32*j];
            s += (e.x + e.y) + (e.z + e.w);
        }
        #pragma unroll
        for (int off = 16; off > 0; off >>= 1)
            s += __shfl_xor_sync(0xffffffffu, s, off);
        if (lane == 0) g_nodemask[base + r] = (s != 0.0f) ? 1 : 0;
    }

    if (tid < HH) {
        int h = tid;
        float x0 = nodes[(size_t)(base+0)*HH + h];
        float x1 = nodes[(size_t)(base+1)*HH + h];
        float x2 = nodes[(size_t)(base+2)*HH + h];
        float x3 = nodes[(size_t)(base+3)*HH + h];
        g_hidden[(size_t)(base+0)*HH + h] = x0;
        g_hidden[(size_t)(base+1)*HH + h] = x1;
        g_hidden[(size_t)(base+2)*HH + h] = x2;
        g_hidden[(size_t)(base+3)*HH + h] = x3;
        sP[h] = make_float4(x0, x1, x2, x3);
    }
    __syncthreads();

    if (tid < HH) {
        int h = tid;
        const ulonglong2* sP2 = (const ulonglong2*)sP;
        u64 v01=0, v23=0, w01=0, w23=0;
        #pragma unroll 4
        for (int k = 0; k < HH; k++) {
            ulonglong2 x = sP2[k];
            u64 wv = pack2(Wv[k*HH + h]);
            u64 ww = pack2(Ww[k*HH + h]);
            v01 = fma2(x.x, wv, v01); v23 = fma2(x.y, wv, v23);
            w01 = fma2(x.x, ww, w01); w23 = fma2(x.y, ww, w23);
        }
        float a,b,c,d, e,f,g,q;
        unpack2(v01, a, b); unpack2(v23, c, d);
        unpack2(w01, e, f); unpack2(w23, g, q);
        g_hv[(size_t)(base+0)*HH + h] = a;
        g_hv[(size_t)(base+1)*HH + h] = b;
        g_hv[(size_t)(base+2)*HH + h] = c;
        g_hv[(size_t)(base+3)*HH + h] = d;
        g_hw[(size_t)(base+0)*HH + h] = e;
        g_hw[(size_t)(base+1)*HH + h] = f;
        g_hw[(size_t)(base+2)*HH + h] = g;
        g_hw[(size_t)(base+3)*HH + h] = q;
    }
}

// ---------------------------------------------------------------------------
// msg: messages[b,v,h] = sum_w [adj!=0] * relu(hv[v,h] + hw[w,h] + e.We)
// Block = 8 v-rows, 256 threads = (vloc 0..7, q 0..31), 4 h per thread
// (h0 = 4q, q < 25 active). hw read as LDG.128 per w (L1-shared by the 8
// warps). Shared: dup'd edge packs 32KB + dup'd masks 8KB = 40KB.
// ---------------------------------------------------------------------------
__global__ void __launch_bounds__(256)
k_msg(const float* __restrict__ edges, const float* __restrict__ We) {
    extern __shared__ u64 sm[];
    u64* s_e2 = sm;           // [(v*128+w)*4 + j] = {e_j, e_j}
    u64* s_m2 = sm + 4096;    // [v*128+w] = {m, m}

    int bx  = blockIdx.x;
    int b   = bx >> 4;
    int v0  = (bx & 15) * 8;
    int tid = threadIdx.x;
    int bN  = b * NN;

    for (int i = tid; i < 1024; i += 256) {
        int v = i >> 7, w = i & 127;
        float4 e = ((const float4*)edges)[(size_t)(bN + v0 + v)*NN + w];
        u64* dst = s_e2 + i*4;
        dst[0] = pack2(e.x); dst[1] = pack2(e.y);
        dst[2] = pack2(e.z); dst[3] = pack2(e.w);
        float s = (e.x + e.y) + (e.z + e.w);
        s_m2[i] = pack2((s != 0.0f) ? 1.0f : 0.0f);
    }
    __syncthreads();

    int vloc = tid >> 5;
    int q    = tid & 31;
    if (q < 25) {
        int h0  = 4*q;
        int row = bN + v0 + vloc;
        float4 hv4 = *(const float4*)(g_hv + (size_t)row*HH + h0);
        u64 hv01 = packlh(hv4.x, hv4.y);
        u64 hv23 = packlh(hv4.z, hv4.w);
        // We pairs for both halves, hoisted
        float4 w0 = *(const float4*)(We + 0*HH + h0);
        float4 w1 = *(const float4*)(We + 1*HH + h0);
        float4 w2 = *(const float4*)(We + 2*HH + h0);
        float4 w3 = *(const float4*)(We + 3*HH + h0);
        u64 we0a = packlh(w0.x, w0.y), we0b = packlh(w0.z, w0.w);
        u64 we1a = packlh(w1.x, w1.y), we1b = packlh(w1.z, w1.w);
        u64 we2a = packlh(w2.x, w2.y), we2b = packlh(w2.z, w2.w);
        u64 we3a = packlh(w3.x, w3.y), we3b = packlh(w3.z, w3.w);

        const u64* ev = s_e2 + vloc*512;
        const u64* mv = s_m2 + vloc*128;
        const float* hwp = g_hw + (size_t)bN*HH + h0;

        u64 acc01 = 0, acc23 = 0;
        #pragma unroll 4
        for (int w = 0; w < NN; w++) {
            float4 hw4 = *(const float4*)(hwp + w*HH);
            u64 hw01 = packlh(hw4.x, hw4.y);
            u64 hw23 = packlh(hw4.z, hw4.w);
            ulonglong2 eA = *(const ulonglong2*)(ev + w*4);
            ulonglong2 eB = *(const ulonglong2*)(ev + w*4 + 2);
            u64 m2v = mv[w];
            u64 p01 = add2(hv01, hw01);
            u64 p23 = add2(hv23, hw23);
            p01 = fma2(eA.x, we0a, p01); p23 = fma2(eA.x, we0b, p23);
            p01 = fma2(eA.y, we1a, p01); p23 = fma2(eA.y, we1b, p23);
            p01 = fma2(eB.x, we2a, p01); p23 = fma2(eB.x, we2b, p23);
            p01 = fma2(eB.y, we3a, p01); p23 = fma2(eB.y, we3b, p23);
            acc01 = fma2(relu2(p01), m2v, acc01);
            acc23 = fma2(relu2(p23), m2v, acc23);
        }
        float4 outv;
        unpack2(acc01, outv.x, outv.y);
        unpack2(acc23, outv.z, outv.w);
        *(float4*)(g_msg + (size_t)row*HH + h0) = outv;
    }
}

// ---------------------------------------------------------------------------
// update (masked tanh) fused with proj of the NEW hidden. 4 rows, 128 thr,
// grid 1024.
// ---------------------------------------------------------------------------
__global__ void __launch_bounds__(128)
k_updproj(const float* __restrict__ Wu, const float* __restrict__ Wv,
          const float* __restrict__ Ww) {
    __shared__ float4 sU[2*HH];      // [hidden; msg] transposed
    __shared__ float4 sP[HH];        // new hidden transposed
    int base = blockIdx.x * 4;
    int tid  = threadIdx.x;
    float* sUf = (float*)sU;

    for (int i = tid; i < 4*2*HH; i += 128) {
        int r = i / (2*HH), k = i - r*(2*HH);
        float x = (k < HH) ? g_hidden[(size_t)(base + r)*HH + k]
                           : g_msg   [(size_t)(base + r)*HH + (k - HH)];
        sUf[k*4 + r] = x;
    }
    __syncthreads();

    if (tid < HH) {
        int h = tid;
        const ulonglong2* sU2 = (const ulonglong2*)sU;
        u64 a01=0, a23=0;
        #pragma unroll 4
        for (int k = 0; k < 2*HH; k++) {
            ulonglong2 x = sU2[k];
            u64 w = pack2(Wu[k*HH + h]);
            a01 = fma2(x.x, w, a01);
            a23 = fma2(x.y, w, a23);
        }
        float f0,f1,f2,f3;
        unpack2(a01, f0, f1); unpack2(a23, f2, f3);
        float n0 = g_nodemask[base+0] ? tanhf(f0) : sUf[h*4+0];
        float n1 = g_nodemask[base+1] ? tanhf(f1) : sUf[h*4+1];
        float n2 = g_nodemask[base+2] ? tanhf(f2) : sUf[h*4+2];
        float n3 = g_nodemask[base+3] ? tanhf(f3) : sUf[h*4+3];
        g_hidden[(size_t)(base+0)*HH + h] = n0;
        g_hidden[(size_t)(base+1)*HH + h] = n1;
        g_hidden[(size_t)(base+2)*HH + h] = n2;
        g_hidden[(size_t)(base+3)*HH + h] = n3;
        sP[h] = make_float4(n0, n1, n2, n3);
    }
    __syncthreads();

    if (tid < HH) {
        int h = tid;
        const ulonglong2* sP2 = (const ulonglong2*)sP;
        u64 v01=0, v23=0, w01=0, w23=0;
        #pragma unroll 4
        for (int k = 0; k < HH; k++) {
            ulonglong2 x = sP2[k];
            u64 wv = pack2(Wv[k*HH + h]);
            u64 ww = pack2(Ww[k*HH + h]);
            v01 = fma2(x.x, wv, v01); v23 = fma2(x.y, wv, v23);
            w01 = fma2(x.x, ww, w01); w23 = fma2(x.y, ww, w23);
        }
        float a,b,c,d, e,f,g,q;
        unpack2(v01, a, b); unpack2(v23, c, d);
        unpack2(w01, e, f); unpack2(w23, g, q);
        g_hv[(size_t)(base+0)*HH + h] = a;
        g_hv[(size_t)(base+1)*HH + h] = b;
        g_hv[(size_t)(base+2)*HH + h] = c;
        g_hv[(size_t)(base+3)*HH + h] = d;
        g_hw[(size_t)(base+0)*HH + h] = e;
        g_hw[(size_t)(base+1)*HH + h] = f;
        g_hw[(size_t)(base+2)*HH + h] = g;
        g_hw[(size_t)(base+3)*HH + h] = q;
    }
}

// ---------------------------------------------------------------------------
// final update fused with readout gterm. No g_hidden write needed.
// ---------------------------------------------------------------------------
__global__ void __launch_bounds__(128)
k_updread(const float* __restrict__ nodes, const float* __restrict__ Wu,
          const float* __restrict__ Wr) {
    __shared__ float4 sU[2*HH];      // [hidden; msg]
    __shared__ float4 sR[2*HH];      // [new_hidden; nodes]
    int base = blockIdx.x * 4;
    int tid  = threadIdx.x;
    float* sUf = (float*)sU;
    float* sRf = (float*)sR;

    for (int i = tid; i < 4*2*HH; i += 128) {
        int r = i / (2*HH), k = i - r*(2*HH);
        float x = (k < HH) ? g_hidden[(size_t)(base + r)*HH + k]
                           : g_msg   [(size_t)(base + r)*HH + (k - HH)];
        sUf[k*4 + r] = x;
    }
    for (int i = tid; i < 4*HH; i += 128) {
        int r = i / HH, k = i - r*HH;
        sRf[(HH + k)*4 + r] = nodes[(size_t)(base + r)*HH + k];
    }
    __syncthreads();

    if (tid < HH) {
        int h = tid;
        const ulonglong2* sU2 = (const ulonglong2*)sU;
        u64 a01=0, a23=0;
        #pragma unroll 4
        for (int k = 0; k < 2*HH; k++) {
            ulonglong2 x = sU2[k];
            u64 w = pack2(Wu[k*HH + h]);
            a01 = fma2(x.x, w, a01);
            a23 = fma2(x.y, w, a23);
        }
        float f0,f1,f2,f3;
        unpack2(a01, f0, f1); unpack2(a23, f2, f3);
        float n0 = g_nodemask[base+0] ? tanhf(f0) : sUf[h*4+0];
        float n1 = g_nodemask[base+1] ? tanhf(f1) : sUf[h*4+1];
        float n2 = g_nodemask[base+2] ? tanhf(f2) : sUf[h*4+2];
        float n3 = g_nodemask[base+3] ? tanhf(f3) : sUf[h*4+3];
        sR[h] = make_float4(n0, n1, n2, n3);
    }
    __syncthreads();

    if (tid < HH) {
        int h = tid;
        const ulonglong2* sR2 = (const ulonglong2*)sR;
        u64 a01=0, a23=0;
        #pragma unroll 4
        for (int k = 0; k < 2*HH; k++) {
            ulonglong2 x = sR2[k];
            u64 w = pack2(Wr[k*HH + h]);
            a01 = fma2(x.x, w, a01);
            a23 = fma2(x.y, w, a23);
        }
        float f0,f1,f2,f3;
        unpack2(a01, f0, f1); unpack2(a23, f2, f3);
        float m0 = g_nodemask[base+0] ? 1.f : 0.f;
        float m1 = g_nodemask[base+1] ? 1.f : 0.f;
        float m2 = g_nodemask[base+2] ? 1.f : 0.f;
        float m3 = g_nodemask[base+3] ? 1.f : 0.f;
        g_gterm[(size_t)(base+0)*HH + h] = fmaxf(f0, 0.f) * m0;
        g_gterm[(size_t)(base+1)*HH + h] = fmaxf(f1, 0.f) * m1;
        g_gterm[(size_t)(base+2)*HH + h] = fmaxf(f2, 0.f) * m2;
        g_gterm[(size_t)(base+3)*HH + h] = fmaxf(f3, 0.f) * m3;
    }
}

// ---------------------------------------------------------------------------
// reduce: out[b,h] = sum_v gterm[b,v,h]  (deterministic, no atomics)
// ---------------------------------------------------------------------------
__global__ void k_reduce(float* __restrict__ out) {
    int b   = blockIdx.x;
    int tid = threadIdx.x;           // 512
    int q   = tid >> 7;
    int h   = tid & 127;
    __shared__ float red[4][128];
    float acc = 0.f;
    if (h < HH) {
        int v0 = q * 32;
        #pragma unroll 4
        for (int v = v0; v < v0 + 32; v++)
            acc += g_gterm[(size_t)(b*NN + v)*HH + h];
    }
    red[q][h] = acc;
    __syncthreads();
    if (q == 0 && h < HH)
        out[b*HH + h] = (red[0][h] + red[1][h]) + (red[2][h] + red[3][h]);
}

extern "C" void kernel_launch(void* const* d_in, const int* in_sizes, int n_in,
                              void* d_out, int out_size) {
    const float* nodes = (const float*)d_in[0];
    const float* edges = (const float*)d_in[1];
    const float* Wv    = (const float*)d_in[2];
    const float* Ww    = (const float*)d_in[3];
    const float* We    = (const float*)d_in[4];
    const float* Wu    = (const float*)d_in[5];
    const float* Wr    = (const float*)d_in[6];
    float* out = (float*)d_out;

    k_init_proj<<<ROWS/4, 128>>>(nodes, edges, Wv, Ww);
    for (int p = 0; p < 2; p++) {
        k_msg<<<512, 256, 40960>>>(edges, We);
        k_updproj<<<ROWS/4, 128>>>(Wu, Wv, Ww);
    }
    k_msg<<<512, 256, 40960>>>(edges, We);
    k_updread<<<ROWS/4, 128>>>(nodes, Wu, Wr);
    k_reduce<<<BB, 512>>>(out);
}